// round 7
// baseline (speedup 1.0000x reference)
#include <cuda_runtime.h>
#include <cuda_bf16.h>
#include <math.h>

#define Hh 128
#define Rr 50
#define Ll 4
#define Nn 10000
#define Mm 64
#define NP 10112           // 316 * 32
#define EMAX 2000000
#define BINS 2048
#define SCALE ((float)BINS / 5.0f)
#define STEP (5.0f / (float)BINS)
#define TBB 64             // bins per table-build block

typedef unsigned long long u64;

__device__ __forceinline__ void fma2(u64 &d, u64 a, u64 b) {
    asm("fma.rn.f32x2 %0, %1, %2, %0;" : "+l"(d) : "l"(a), "l"(b));
}
__device__ __forceinline__ u64 pack2(float lo, float hi) {
    u64 r; asm("mov.b64 %0, {%1, %2};" : "=l"(r) : "f"(lo), "f"(hi)); return r;
}
__device__ __forceinline__ void unpack2(u64 v, float &lo, float &hi) {
    asm("mov.b64 {%0, %1}, %2;" : "=f"(lo), "=f"(hi) : "l"(v));
}
__device__ __forceinline__ float tanhap(float x) {
    float r; asm("tanh.approx.f32 %0, %1;" : "=f"(r) : "f"(x)); return r;
}
__device__ __forceinline__ float sigap(float x) {
    return fmaf(tanhap(x * 0.5f), 0.5f, 0.5f);
}

// ---------------- scratch ----------------
__device__ float  g_x[NP * Hh];
__device__ float  g_y[NP * Hh];
__device__ float  g_S[NP * Hh];
__device__ float  g_d[EMAX];
__device__ int    g_rp[Nn + 1];
__device__ float  g_sums[Mm * Hh];
__device__ float  g_cnt[Mm];
__device__ float2 g_tab[Ll * BINS * Hh];
__device__ u64    g_Wcd[Ll * Hh * 3 * Hh];    // duplicated-pair Wc = W2@W_ih
__device__ u64    g_W1ad[Ll * Hh * Hh];       // duplicated-pair W1a
__device__ float  g_bc2[Ll * 3 * Hh];
__device__ int    g_ctr;

// ---------------- prep0: init x (+pads), zero sums/cnt, build row_ptr ----------------
__global__ void prep0(const int* __restrict__ an, const float* __restrict__ emb,
                      const int* __restrict__ rowp, int E,
                      float* __restrict__ x, float* __restrict__ sums,
                      float* __restrict__ cnt, int* __restrict__ rp) {
    int i = blockIdx.x * blockDim.x + threadIdx.x;
    if (i < NP * Hh) {
        int n = i >> 7, ch = i & 127;
        if (n < Nn) {
            int a = an[n];
            a = a < 0 ? 0 : (a > 99 ? 99 : a);
            x[i] = emb[a * Hh + ch];
        } else {
            x[i] = 0.f;
        }
        return;
    }
    int i2 = i - NP * Hh;
    if (i2 < Mm * Hh) { sums[i2] = 0.f; return; }
    i2 -= Mm * Hh;
    if (i2 < Mm) { cnt[i2] = 0.f; return; }
    int e = i2 - Mm;
    if (e > E) return;
    if (e == 0) {
        int b = rowp[0];
        for (int r = 0; r <= b; r++) rp[r] = 0;
    } else if (e == E) {
        int a = rowp[E - 1];
        for (int r = a + 1; r <= Nn; r++) rp[r] = E;
    } else {
        int a = rowp[e - 1], b = rowp[e];
        for (int r = a + 1; r <= b; r++) rp[r] = e;
    }
}

// ---------------- prep1: distances + float2 rbf table (tiled) + bc2 + W1ad ----------------
__global__ void prep1(const float* __restrict__ pos, const int* __restrict__ rowp,
                      const int* __restrict__ colp, int E, int ndb,
                      const float* __restrict__ W1, const float* __restrict__ W_ih,
                      const float* __restrict__ b2,
                      float* __restrict__ dv, float2* __restrict__ tab,
                      float* __restrict__ bc2, u64* __restrict__ W1ad) {
    __shared__ float basis[(TBB + 1) * Rr];
    int tid = threadIdx.x;
    int blk = blockIdx.x;
    if (blk < ndb) {
        int e = blk * 128 + tid;
        if (e < E) {
            int r = rowp[e], c = colp[e];
            float dx = pos[r * 3 + 0] - pos[c * 3 + 0];
            float dy = pos[r * 3 + 1] - pos[c * 3 + 1];
            float dz = pos[r * 3 + 2] - pos[c * 3 + 2];
            dv[e] = sqrtf(dx * dx + dy * dy + dz * dz);
        }
        return;
    }
    int t = blk - ndb;
    const int TBLKS = BINS / TBB;                 // 32 per layer
    if (t < TBLKS * Ll) {
        int l = t / TBLKS, bt = t - l * TBLKS;
        int bin0 = bt * TBB;
        for (int i = tid; i < (TBB + 1) * Rr; i += 128) {
            int g = i / Rr, k = i - g * Rr;
            float c = (float)k * (5.0f / 49.0f);
            float d0 = (float)(bin0 + g) * STEP - c;
            basis[i] = expf(-50.0f * d0 * d0);
        }
        __syncthreads();
        const float* W1b = W1 + l * (Hh + Rr) * Hh + Hh * Hh;
        float w[Rr];
#pragma unroll
        for (int k = 0; k < Rr; k++) w[k] = W1b[k * Hh + tid];
        float vprev = 0.f;
#pragma unroll
        for (int k = 0; k < Rr; k++) vprev += basis[k] * w[k];
        for (int g = 1; g <= TBB; g++) {
            float v = 0.f;
            const float* bs = &basis[g * Rr];
#pragma unroll
            for (int k = 0; k < Rr; k++) v += bs[k] * w[k];
            tab[((l * BINS + bin0 + g - 1) << 7) + tid] = make_float2(vprev, v - vprev);
            vprev = v;
        }
        return;
    }
    int t2 = t - TBLKS * Ll;
    if (t2 < 12) {                      // bc2 = b2 @ W_ih
        int l = t2 / 3, chunk = t2 - l * 3;
        int n = chunk * 128 + tid;
        const float* W = W_ih + l * Hh * 3 * Hh;
        const float* b = b2 + l * Hh;
        float s = 0.f;
#pragma unroll 8
        for (int k = 0; k < Hh; k++) s += b[k] * W[k * 3 * Hh + n];
        bc2[l * 3 * Hh + n] = s;
        return;
    }
    int t3 = t2 - 12;                   // [0, 32): W1ad duplicated build
    int l = t3 >> 3, rc = t3 & 7;
    const float* Wsrc = W1 + (size_t)l * (Hh + Rr) * Hh;
    for (int r = rc * 16; r < rc * 16 + 16; r++) {
        float v = Wsrc[r * Hh + tid];
        W1ad[(size_t)l * Hh * Hh + r * Hh + tid] = pack2(v, v);
    }
}

// ---------------- small f32x2 GEMM: Wcd = dup(W2 @ W_ih), all layers ----------------
__global__ void __launch_bounds__(256)
gemm_wc(const float* __restrict__ A, const float* __restrict__ B,
        u64* __restrict__ Cd, int Nr, int aSz, int bSz, int cSz) {
    __shared__ float As[16][132];
    __shared__ float Bs[16][64];
    int tid = threadIdx.x;
    int tx = tid & 15, ty = tid >> 4;
    int n0 = blockIdx.x * 64;
    const float* Ab = A + (size_t)blockIdx.z * aSz;
    const float* Bb = B + (size_t)blockIdx.z * bSz;
    u64* Cb = Cd + (size_t)blockIdx.z * cSz;
    u64 acc[4][4] = {};
    for (int kk = 0; kk < 128; kk += 16) {
#pragma unroll
        for (int it = 0; it < 2; it++) {
            int r = (tid >> 2) + it * 64;
            int c4 = (tid & 3) << 2;
            float4 v = *(const float4*)(Ab + (size_t)r * 128 + kk + c4);
            As[c4 + 0][r] = v.x; As[c4 + 1][r] = v.y;
            As[c4 + 2][r] = v.z; As[c4 + 3][r] = v.w;
        }
        {
            int r = tid >> 4, c4 = (tid & 15) << 2;
            *(float4*)&Bs[r][c4] = *(const float4*)(Bb + (size_t)(kk + r) * Nr + n0 + c4);
        }
        __syncthreads();
#pragma unroll
        for (int k = 0; k < 16; k++) {
            longlong2 la = *(const longlong2*)&As[k][ty * 8];
            longlong2 lb = *(const longlong2*)&As[k][ty * 8 + 4];
            float4 bv = *(const float4*)&Bs[k][tx * 4];
            u64 ap[4] = { (u64)la.x, (u64)la.y, (u64)lb.x, (u64)lb.y };
            u64 bp[4] = { pack2(bv.x, bv.x), pack2(bv.y, bv.y),
                          pack2(bv.z, bv.z), pack2(bv.w, bv.w) };
#pragma unroll
            for (int i = 0; i < 4; i++)
#pragma unroll
                for (int j = 0; j < 4; j++) fma2(acc[i][j], ap[i], bp[j]);
        }
        __syncthreads();
    }
#pragma unroll
    for (int i = 0; i < 4; i++) {
        int mA = ty * 8 + 2 * i;
#pragma unroll
        for (int j = 0; j < 4; j++) {
            float lo, hi;
            unpack2(acc[i][j], lo, hi);
            Cb[(size_t)mA * Nr + n0 + tx * 4 + j] = pack2(lo, lo);
            Cb[(size_t)(mA + 1) * Nr + n0 + tx * 4 + j] = pack2(hi, hi);
        }
    }
}

// ---------------- fused update: gi = S@Wc (+biases), x' = x+gru(gi), y = x'@W1a + b1 ----
// 32-row tiles. S==null: y = x@W1a only. W1ad==null: skip y phase (final layer).
__global__ void __launch_bounds__(256, 2)
update_gemm(const float* __restrict__ S, const u64* __restrict__ Wcd,
            const float* __restrict__ b_ih, const int* __restrict__ rp,
            const float* __restrict__ bc2, const float* __restrict__ bhh,
            const float* __restrict__ xin, float* __restrict__ xio,
            const u64* __restrict__ W1ad, const float* __restrict__ b1,
            float* __restrict__ yout) {
    __shared__ float As[8][36];
    __shared__ u64   Bsd[8][388];
    __shared__ float sdeg[32];
    __shared__ float sbih[384], sbc2[384], sbhh[384];
    int tid = threadIdx.x;
    int tx = tid & 15, ty = tid >> 4;
    int m0 = blockIdx.x * 32;
    int mA = m0 + ty * 2;

    if (S) {
        if (tid < 32) {
            int m = m0 + tid;
            sdeg[tid] = (m < Nn) ? (float)(__ldg(rp + m + 1) - __ldg(rp + m)) : 0.f;
        }
        for (int i = tid; i < 384; i += 256) {
            sbih[i] = b_ih[i];
            sbc2[i] = bc2[i];
            sbhh[i] = bhh[i];
        }
        u64 acc[24];
#pragma unroll
        for (int j = 0; j < 24; j++) acc[j] = 0ull;
#pragma unroll 1
        for (int kk = 0; kk < 128; kk += 8) {
            {
                int r = tid >> 3, c = tid & 7;
                As[c][r] = __ldg(S + (size_t)(m0 + r) * 128 + kk + c);
            }
#pragma unroll
            for (int t = 0; t < 6; t++) {
                int id = tid + t * 256;
                int r = id / 192, c2 = (id - r * 192) * 2;
                *(uint4*)&Bsd[r][c2] = __ldg((const uint4*)(Wcd + (size_t)(kk + r) * 384 + c2));
            }
            __syncthreads();
#pragma unroll
            for (int k = 0; k < 8; k++) {
                u64 la = *(const u64*)&As[k][ty * 2];
#pragma unroll
                for (int g = 0; g < 3; g++) {
                    u64 b[8];
                    *(uint4*)&b[0] = *(const uint4*)&Bsd[k][g * 128 + tx * 8];
                    *(uint4*)&b[2] = *(const uint4*)&Bsd[k][g * 128 + tx * 8 + 2];
                    *(uint4*)&b[4] = *(const uint4*)&Bsd[k][g * 128 + tx * 8 + 4];
                    *(uint4*)&b[6] = *(const uint4*)&Bsd[k][g * 128 + tx * 8 + 6];
#pragma unroll
                    for (int jj = 0; jj < 8; jj++) fma2(acc[g * 8 + jj], la, b[jj]);
                }
            }
            __syncthreads();
        }
        // ---- phase 2: GRU in registers ----
        float dg0 = sdeg[ty * 2], dg1 = sdeg[ty * 2 + 1];
        float4 x0a = *(const float4*)(xin + (size_t)mA * 128 + tx * 8);
        float4 x0b = *(const float4*)(xin + (size_t)mA * 128 + tx * 8 + 4);
        float4 x1a = *(const float4*)(xin + (size_t)(mA + 1) * 128 + tx * 8);
        float4 x1b = *(const float4*)(xin + (size_t)(mA + 1) * 128 + tx * 8 + 4);
        float xo0[8] = { x0a.x, x0a.y, x0a.z, x0a.w, x0b.x, x0b.y, x0b.z, x0b.w };
        float xo1[8] = { x1a.x, x1a.y, x1a.z, x1a.w, x1b.x, x1b.y, x1b.z, x1b.w };
        float xn0[8], xn1[8];
#pragma unroll
        for (int jj = 0; jj < 8; jj++) {
            int c = tx * 8 + jj;
            float bR = sbih[c],       bZ = sbih[128 + c],  bN = sbih[256 + c];
            float cR = sbc2[c],       cZ = sbc2[128 + c],  cN = sbc2[256 + c];
            float hR = sbhh[c],       hZ = sbhh[128 + c],  hN = sbhh[256 + c];
            float lR, hRr, lZ, hZr, lN, hNr;
            unpack2(acc[jj], lR, hRr);
            unpack2(acc[8 + jj], lZ, hZr);
            unpack2(acc[16 + jj], lN, hNr);
            // row 0
            {
                float gR = lR + bR + dg0 * cR + hR;
                float gZ = lZ + bZ + dg0 * cZ + hZ;
                float gN = lN + bN + dg0 * cN;
                float r = sigap(gR);
                float z = sigap(gZ);
                float n = tanhap(fmaf(r, hN, gN));
                xn0[jj] = fmaf(-z, n, xo0[jj] + n);
            }
            // row 1
            {
                float gR = hRr + bR + dg1 * cR + hR;
                float gZ = hZr + bZ + dg1 * cZ + hZ;
                float gN = hNr + bN + dg1 * cN;
                float r = sigap(gR);
                float z = sigap(gZ);
                float n = tanhap(fmaf(r, hN, gN));
                xn1[jj] = fmaf(-z, n, xo1[jj] + n);
            }
        }
        *(float4*)(xio + (size_t)mA * 128 + tx * 8)     = make_float4(xn0[0], xn0[1], xn0[2], xn0[3]);
        *(float4*)(xio + (size_t)mA * 128 + tx * 8 + 4) = make_float4(xn0[4], xn0[5], xn0[6], xn0[7]);
        *(float4*)(xio + (size_t)(mA + 1) * 128 + tx * 8)     = make_float4(xn1[0], xn1[1], xn1[2], xn1[3]);
        *(float4*)(xio + (size_t)(mA + 1) * 128 + tx * 8 + 4) = make_float4(xn1[4], xn1[5], xn1[6], xn1[7]);
    }
    if (!W1ad) return;
    __syncthreads();
    const float* xsrc = S ? xio : xin;
    // ---- phase 3: y = x' @ W1a + b1 ----
    u64 acc2[8];
#pragma unroll
    for (int j = 0; j < 8; j++) acc2[j] = 0ull;
#pragma unroll 1
    for (int kk = 0; kk < 128; kk += 8) {
        {
            int r = tid >> 3, c = tid & 7;
            As[c][r] = xsrc[(size_t)(m0 + r) * 128 + kk + c];
        }
#pragma unroll
        for (int t = 0; t < 2; t++) {
            int id = tid + t * 256;
            int r = id >> 6, c2 = (id & 63) * 2;
            *(uint4*)&Bsd[r][c2] = __ldg((const uint4*)(W1ad + (size_t)(kk + r) * 128 + c2));
        }
        __syncthreads();
#pragma unroll
        for (int k = 0; k < 8; k++) {
            u64 la = *(const u64*)&As[k][ty * 2];
            u64 b[8];
            *(uint4*)&b[0] = *(const uint4*)&Bsd[k][tx * 8];
            *(uint4*)&b[2] = *(const uint4*)&Bsd[k][tx * 8 + 2];
            *(uint4*)&b[4] = *(const uint4*)&Bsd[k][tx * 8 + 4];
            *(uint4*)&b[6] = *(const uint4*)&Bsd[k][tx * 8 + 6];
#pragma unroll
            for (int jj = 0; jj < 8; jj++) fma2(acc2[jj], la, b[jj]);
        }
        __syncthreads();
    }
    float4 b1a = __ldg((const float4*)(b1 + tx * 8));
    float4 b1b = __ldg((const float4*)(b1 + tx * 8 + 4));
    float bb[8] = { b1a.x, b1a.y, b1a.z, b1a.w, b1b.x, b1b.y, b1b.z, b1b.w };
    float y0[8], y1[8];
#pragma unroll
    for (int jj = 0; jj < 8; jj++) {
        float lo, hi;
        unpack2(acc2[jj], lo, hi);
        y0[jj] = lo + bb[jj];
        y1[jj] = hi + bb[jj];
    }
    *(float4*)(yout + (size_t)mA * 128 + tx * 8)     = make_float4(y0[0], y0[1], y0[2], y0[3]);
    *(float4*)(yout + (size_t)mA * 128 + tx * 8 + 4) = make_float4(y0[4], y0[5], y0[6], y0[7]);
    *(float4*)(yout + (size_t)(mA + 1) * 128 + tx * 8)     = make_float4(y1[0], y1[1], y1[2], y1[3]);
    *(float4*)(yout + (size_t)(mA + 1) * 128 + tx * 8 + 4) = make_float4(y1[4], y1[5], y1[6], y1[7]);
}

// ---------------- warp-per-node CSR edge kernel, tanh-silu ----------------
__global__ void __launch_bounds__(128)
edge_csr(const int* __restrict__ rp, const int* __restrict__ colp,
         const float* __restrict__ dvec, const float* __restrict__ y,
         const float2* __restrict__ tab, float* __restrict__ S) {
    int lane = threadIdx.x & 31;
    int n = blockIdx.x * 4 + (threadIdx.x >> 5);
    if (n >= Nn) return;
    int e0 = rp[n];
    int deg = rp[n + 1] - e0;
    const float* tf = (const float*)tab;
    float a0 = 0.f, a1 = 0.f, a2 = 0.f, a3 = 0.f;
    for (int base = 0; base < deg; base += 32) {
        int cnt = min(32, deg - base);
        float u_r = 0.f; int cc_r = 0;
        if (lane < cnt) {
            u_r = __ldg(dvec + e0 + base + lane) * SCALE;
            cc_r = __ldg(colp + e0 + base + lane);
        }
        for (int j = 0; j < cnt; j++) {
            float u = __shfl_sync(~0u, u_r, j);
            int cc = __shfl_sync(~0u, cc_r, j);
            int b = (int)u;
            float f = u - (float)b;
            const float4* trow = (const float4*)(tf + (b << 8)) + lane * 2;
            float4 t0 = __ldg(trow);
            float4 t1 = __ldg(trow + 1);
            float4 yv = __ldg((const float4*)(y + ((size_t)cc << 7)) + lane);
            float h0 = 0.5f * (yv.x + fmaf(f, t0.y, t0.x));
            float h1 = 0.5f * (yv.y + fmaf(f, t0.w, t0.z));
            float h2 = 0.5f * (yv.z + fmaf(f, t1.y, t1.x));
            float h3 = 0.5f * (yv.w + fmaf(f, t1.w, t1.z));
            a0 += fmaf(h0, tanhap(h0), h0);
            a1 += fmaf(h1, tanhap(h1), h1);
            a2 += fmaf(h2, tanhap(h2), h2);
            a3 += fmaf(h3, tanhap(h3), h3);
        }
    }
    *(float4*)(S + ((size_t)n << 7) + lane * 4) = make_float4(a0, a1, a2, a3);
}

// ---------------- LayerNorm + pooling (+final via last block) ----------------
__global__ void __launch_bounds__(256)
ln_pool_all(const float* __restrict__ x, const int* __restrict__ batch,
            const float* __restrict__ lg, const float* __restrict__ lb,
            float* __restrict__ out, float* __restrict__ sums,
            float* __restrict__ cnt, float* __restrict__ out2) {
    __shared__ int s_last;
    int warp = (blockIdx.x * blockDim.x + threadIdx.x) >> 5;
    int lane = threadIdx.x & 31;
    if (warp < Nn) {
        int ch = lane * 4;
        float4 v = __ldg((const float4*)(x + (size_t)warp * Hh + ch));
        float s = v.x + v.y + v.z + v.w;
#pragma unroll
        for (int o = 16; o; o >>= 1) s += __shfl_xor_sync(~0u, s, o);
        float mu = s * (1.0f / 128.0f);
        float dx = v.x - mu, dy = v.y - mu, dz = v.z - mu, dw = v.w - mu;
        float vs = dx * dx + dy * dy + dz * dz + dw * dw;
#pragma unroll
        for (int o = 16; o; o >>= 1) vs += __shfl_xor_sync(~0u, vs, o);
        float inv = rsqrtf(vs * (1.0f / 128.0f) + 1e-5f);
        float o0 = dx * inv * lg[ch + 0] + lb[ch + 0];
        float o1 = dy * inv * lg[ch + 1] + lb[ch + 1];
        float o2 = dz * inv * lg[ch + 2] + lb[ch + 2];
        float o3 = dw * inv * lg[ch + 3] + lb[ch + 3];
        *(float4*)(out + (size_t)warp * Hh + ch) = make_float4(o0, o1, o2, o3);
        int bm = batch[warp];
        atomicAdd(&sums[bm * Hh + ch + 0], o0);
        atomicAdd(&sums[bm * Hh + ch + 1], o1);
        atomicAdd(&sums[bm * Hh + ch + 2], o2);
        atomicAdd(&sums[bm * Hh + ch + 3], o3);
        if (lane == 0) atomicAdd(&cnt[bm], 1.0f);
    }
    __syncthreads();
    if (threadIdx.x == 0) {
        __threadfence();
        int t = atomicAdd(&g_ctr, 1);
        s_last = (t == gridDim.x - 1) ? 1 : 0;
    }
    __syncthreads();
    if (s_last) {
        for (int i = threadIdx.x; i < Mm * Hh; i += blockDim.x) {
            float c = cnt[i >> 7];
            out2[i] = sums[i] / (c < 1.f ? 1.f : c);
        }
        if (threadIdx.x == 0) g_ctr = 0;
    }
}

// ---------------- host launcher ----------------
extern "C" void kernel_launch(void* const* d_in, const int* in_sizes, int n_in,
                              void* d_out, int out_size) {
    const int*   an    = (const int*)d_in[0];
    const float* pos   = (const float*)d_in[1];
    const int*   batch = (const int*)d_in[2];
    const int*   eidx  = (const int*)d_in[3];
    const float* emb   = (const float*)d_in[4];
    const float* W1    = (const float*)d_in[5];
    const float* b1    = (const float*)d_in[6];
    const float* W2    = (const float*)d_in[7];
    const float* b2    = (const float*)d_in[8];
    const float* W_ih  = (const float*)d_in[9];
    const float* b_ih  = (const float*)d_in[10];
    const float* b_hh  = (const float*)d_in[11];
    const float* ln_g  = (const float*)d_in[12];
    const float* ln_b  = (const float*)d_in[13];
    int E = in_sizes[3] / 2;
    if (E > EMAX) E = EMAX;
    const int* rowp = eidx;
    const int* colp = eidx + E;
    float* out = (float*)d_out;

    float *xp, *yp, *Sp, *dvp, *sp, *cp, *bcp;
    float2* tp;
    u64 *wcdp, *w1adp;
    int* rpp;
    cudaGetSymbolAddress((void**)&xp,   g_x);
    cudaGetSymbolAddress((void**)&yp,   g_y);
    cudaGetSymbolAddress((void**)&Sp,   g_S);
    cudaGetSymbolAddress((void**)&dvp,  g_d);
    cudaGetSymbolAddress((void**)&rpp,  g_rp);
    cudaGetSymbolAddress((void**)&sp,   g_sums);
    cudaGetSymbolAddress((void**)&cp,   g_cnt);
    cudaGetSymbolAddress((void**)&tp,   g_tab);
    cudaGetSymbolAddress((void**)&wcdp, g_Wcd);
    cudaGetSymbolAddress((void**)&w1adp, g_W1ad);
    cudaGetSymbolAddress((void**)&bcp,  g_bc2);

    // 1: init x/pads + zero sums/cnt + row_ptr
    int p0n = NP * Hh + Mm * Hh + Mm + E + 1;
    prep0<<<(p0n + 255) / 256, 256>>>(an, emb, rowp, E, xp, sp, cp, rpp);
    // 2: distances + float2 table + bc2 + W1ad
    int ndb = (E + 127) / 128;
    prep1<<<ndb + (BINS / TBB) * Ll + 12 + 32, 128>>>(pos, rowp, colp, E, ndb,
                                                      W1, W_ih, b2, dvp, tp, bcp, w1adp);
    // 3: Wcd = dup(W2 @ W_ih), all layers
    gemm_wc<<<dim3(6, 1, Ll), 256>>>(W2, W_ih, wcdp, 3 * Hh,
                                     Hh * Hh, Hh * 3 * Hh, Hh * 3 * Hh);
    const int UB = NP / 32;   // 316
    // 4: y = x @ W1a[0] + b1[0]
    update_gemm<<<UB, 256>>>(nullptr, nullptr, nullptr, nullptr, nullptr, nullptr,
                             xp, xp, w1adp, b1, yp);
    for (int l = 0; l < Ll; l++) {
        edge_csr<<<(Nn + 3) / 4, 128>>>(rpp, colp, dvp, yp, tp + l * BINS * Hh, Sp);
        const u64* wy = (l < 3) ? (w1adp + (size_t)(l + 1) * Hh * Hh) : nullptr;
        const float* by = (l < 3) ? (b1 + (l + 1) * Hh) : nullptr;
        update_gemm<<<UB, 256>>>(Sp, wcdp + (size_t)l * Hh * 3 * Hh,
                                 b_ih + l * 3 * Hh, rpp, bcp + l * 3 * Hh,
                                 b_hh + l * 3 * Hh, xp, xp, wy, by, yp);
    }

    float* out_x = out;
    float* out_rep = out + Nn * Hh;
    if (out_size == Mm * Hh) { out_x = yp; out_rep = out; }
    ln_pool_all<<<(Nn + 7) / 8, 256>>>(xp, batch, ln_g, ln_b, out_x, sp, cp, out_rep);
}

// round 8
// speedup vs baseline: 4.3960x; 4.3960x over previous
#include <cuda_runtime.h>
#include <cuda_bf16.h>
#include <math.h>

#define Hh 128
#define Rr 50
#define Ll 4
#define Nn 10000
#define Mm 64
#define NP 10112           // 79 * 128
#define EMAX 2000000
#define BINS 2048
#define SCALE ((float)BINS / 5.0f)
#define STEP (5.0f / (float)BINS)
#define TBB 64             // bins per table-build block

typedef unsigned long long u64;

__device__ __forceinline__ void fma2(u64 &d, u64 a, u64 b) {
    asm("fma.rn.f32x2 %0, %1, %2, %0;" : "+l"(d) : "l"(a), "l"(b));
}
__device__ __forceinline__ u64 pack2(float lo, float hi) {
    u64 r; asm("mov.b64 %0, {%1, %2};" : "=l"(r) : "f"(lo), "f"(hi)); return r;
}
__device__ __forceinline__ void unpack2(u64 v, float &lo, float &hi) {
    asm("mov.b64 {%0, %1}, %2;" : "=f"(lo), "=f"(hi) : "l"(v));
}
__device__ __forceinline__ float tanhap(float x) {
    float r; asm("tanh.approx.f32 %0, %1;" : "=f"(r) : "f"(x)); return r;
}

__device__ __forceinline__ float gru_upd(float xo, float rv, float zv, float nv,
                                         float bhr, float bhz, float bhn) {
    float r = __fdividef(1.f, 1.f + __expf(-(rv + bhr)));
    float z = __fdividef(1.f, 1.f + __expf(-(zv + bhz)));
    float t = nv + r * bhn;
    float e = __expf(2.f * t);
    float th = 1.f - __fdividef(2.f, e + 1.f);
    return xo + (1.f - z) * th;
}

// ---------------- scratch ----------------
__device__ float  g_x[NP * Hh];
__device__ float  g_y[NP * Hh];
__device__ float  g_S[NP * Hh];
__device__ float  g_gi[NP * 3 * Hh];
__device__ float  g_d[EMAX];
__device__ int    g_rp[Nn + 1];
__device__ float  g_sums[Mm * Hh];
__device__ float  g_cnt[Mm];
__device__ float2 g_tab[Ll * BINS * Hh];
__device__ float  g_Wc[Ll * Hh * 3 * Hh];
__device__ float  g_bc2[Ll * 3 * Hh];
__device__ int    g_ctr;

// ---------------- prep0: init x (+pads), zero sums/cnt, build row_ptr ----------------
__global__ void prep0(const int* __restrict__ an, const float* __restrict__ emb,
                      const int* __restrict__ rowp, int E,
                      float* __restrict__ x, float* __restrict__ sums,
                      float* __restrict__ cnt, int* __restrict__ rp) {
    int i = blockIdx.x * blockDim.x + threadIdx.x;
    if (i < NP * Hh) {
        int n = i >> 7, ch = i & 127;
        if (n < Nn) {
            int a = an[n];
            a = a < 0 ? 0 : (a > 99 ? 99 : a);
            x[i] = emb[a * Hh + ch];
        } else {
            x[i] = 0.f;
        }
        return;
    }
    int i2 = i - NP * Hh;
    if (i2 < Mm * Hh) { sums[i2] = 0.f; return; }
    i2 -= Mm * Hh;
    if (i2 < Mm) { cnt[i2] = 0.f; return; }
    int e = i2 - Mm;
    if (e > E) return;
    if (e == 0) {
        int b = rowp[0];
        for (int r = 0; r <= b; r++) rp[r] = 0;
    } else if (e == E) {
        int a = rowp[E - 1];
        for (int r = a + 1; r <= Nn; r++) rp[r] = E;
    } else {
        int a = rowp[e - 1], b = rowp[e];
        for (int r = a + 1; r <= b; r++) rp[r] = e;
    }
}

// ---------------- prep1: distances + float2 rbf table (tiled) + bc2 ----------------
__global__ void prep1(const float* __restrict__ pos, const int* __restrict__ rowp,
                      const int* __restrict__ colp, int E, int ndb,
                      const float* __restrict__ W1, const float* __restrict__ W_ih,
                      const float* __restrict__ b2,
                      float* __restrict__ dv, float2* __restrict__ tab,
                      float* __restrict__ bc2) {
    __shared__ float basis[(TBB + 1) * Rr];
    int tid = threadIdx.x;
    int blk = blockIdx.x;
    if (blk < ndb) {
        int e = blk * 128 + tid;
        if (e < E) {
            int r = rowp[e], c = colp[e];
            float dx = pos[r * 3 + 0] - pos[c * 3 + 0];
            float dy = pos[r * 3 + 1] - pos[c * 3 + 1];
            float dz = pos[r * 3 + 2] - pos[c * 3 + 2];
            dv[e] = sqrtf(dx * dx + dy * dy + dz * dz);
        }
        return;
    }
    int t = blk - ndb;
    const int TBLKS = BINS / TBB;                 // 32 per layer
    if (t < TBLKS * Ll) {
        int l = t / TBLKS, bt = t - l * TBLKS;
        int bin0 = bt * TBB;
        for (int i = tid; i < (TBB + 1) * Rr; i += 128) {
            int g = i / Rr, k = i - g * Rr;
            float c = (float)k * (5.0f / 49.0f);
            float d0 = (float)(bin0 + g) * STEP - c;
            basis[i] = expf(-50.0f * d0 * d0);
        }
        __syncthreads();
        const float* W1b = W1 + l * (Hh + Rr) * Hh + Hh * Hh;
        float w[Rr];
#pragma unroll
        for (int k = 0; k < Rr; k++) w[k] = W1b[k * Hh + tid];
        float vprev = 0.f;
#pragma unroll
        for (int k = 0; k < Rr; k++) vprev += basis[k] * w[k];
        for (int g = 1; g <= TBB; g++) {
            float v = 0.f;
            const float* bs = &basis[g * Rr];
#pragma unroll
            for (int k = 0; k < Rr; k++) v += bs[k] * w[k];
            tab[((l * BINS + bin0 + g - 1) << 7) + tid] = make_float2(vprev, v - vprev);
            vprev = v;
        }
        return;
    }
    int t2 = t - TBLKS * Ll;           // [0, 12): bc2 = b2 @ W_ih
    int l = t2 / 3, chunk = t2 - l * 3;
    int n = chunk * 128 + tid;
    const float* W = W_ih + l * Hh * 3 * Hh;
    const float* b = b2 + l * Hh;
    float s = 0.f;
#pragma unroll 8
    for (int k = 0; k < Hh; k++) s += b[k] * W[k * 3 * Hh + n];
    bc2[l * 3 * Hh + n] = s;
}

// ---------------- f32x2 GEMM, tile 128x128, optional fused GRU prologue ----------------
__global__ void __launch_bounds__(256, 2)
gemm_f2b(const float* __restrict__ A, const float* __restrict__ B,
         const float* __restrict__ bias, const int* __restrict__ rp,
         const float* __restrict__ bias2,
         const float* __restrict__ gi, const float* __restrict__ bhh,
         float* __restrict__ xout,
         float* __restrict__ C, int Nr,
         int aSz, int bSz, int cSz) {
    __shared__ float As[16][132];
    __shared__ float Bs[16][128];
    int tid = threadIdx.x;
    int tx = tid & 15, ty = tid >> 4;
    int m0 = blockIdx.y * 128, n0 = blockIdx.x * 128;
    const float* Ab = A + (size_t)blockIdx.z * aSz;
    const float* Bb = B + (size_t)blockIdx.z * bSz;
    float* Cb = C + (size_t)blockIdx.z * cSz;
    u64 acc[4][8] = {};
    for (int kk = 0; kk < 128; kk += 16) {
#pragma unroll
        for (int it = 0; it < 2; it++) {
            int r = (tid >> 2) + it * 64;
            int c4 = (tid & 3) << 2;
            int m = m0 + r;
            float4 v = *(const float4*)(Ab + (size_t)m * 128 + kk + c4);
            if (gi) {
                const float* gm = gi + (size_t)m * 384 + kk + c4;
                float4 rv = __ldg((const float4*)(gm));
                float4 zv = __ldg((const float4*)(gm + 128));
                float4 nv = __ldg((const float4*)(gm + 256));
                float4 br = __ldg((const float4*)(bhh + kk + c4));
                float4 bz = __ldg((const float4*)(bhh + 128 + kk + c4));
                float4 bn = __ldg((const float4*)(bhh + 256 + kk + c4));
                v.x = gru_upd(v.x, rv.x, zv.x, nv.x, br.x, bz.x, bn.x);
                v.y = gru_upd(v.y, rv.y, zv.y, nv.y, br.y, bz.y, bn.y);
                v.z = gru_upd(v.z, rv.z, zv.z, nv.z, br.z, bz.z, bn.z);
                v.w = gru_upd(v.w, rv.w, zv.w, nv.w, br.w, bz.w, bn.w);
                *(float4*)(xout + (size_t)m * 128 + kk + c4) = v;
            }
            As[c4 + 0][r] = v.x; As[c4 + 1][r] = v.y;
            As[c4 + 2][r] = v.z; As[c4 + 3][r] = v.w;
        }
        {
            int r = tid >> 4, c8 = (tid & 15) << 3;
            *(float4*)&Bs[r][c8]     = *(const float4*)(Bb + (size_t)(kk + r) * Nr + n0 + c8);
            *(float4*)&Bs[r][c8 + 4] = *(const float4*)(Bb + (size_t)(kk + r) * Nr + n0 + c8 + 4);
        }
        __syncthreads();
#pragma unroll
        for (int k = 0; k < 16; k++) {
            longlong2 la = *(const longlong2*)&As[k][ty * 8];
            longlong2 lb = *(const longlong2*)&As[k][ty * 8 + 4];
            float4 b0 = *(const float4*)&Bs[k][tx * 8];
            float4 b1 = *(const float4*)&Bs[k][tx * 8 + 4];
            u64 ap[4] = { (u64)la.x, (u64)la.y, (u64)lb.x, (u64)lb.y };
            u64 bp[8] = { pack2(b0.x, b0.x), pack2(b0.y, b0.y),
                          pack2(b0.z, b0.z), pack2(b0.w, b0.w),
                          pack2(b1.x, b1.x), pack2(b1.y, b1.y),
                          pack2(b1.z, b1.z), pack2(b1.w, b1.w) };
#pragma unroll
            for (int i = 0; i < 4; i++)
#pragma unroll
                for (int j = 0; j < 8; j++) fma2(acc[i][j], ap[i], bp[j]);
        }
        __syncthreads();
    }
    float4 bb0 = make_float4(0.f, 0.f, 0.f, 0.f), bb1 = bb0;
    float4 c20 = bb0, c21 = bb0;
    if (bias)  { bb0 = *(const float4*)(bias + n0 + tx * 8);
                 bb1 = *(const float4*)(bias + n0 + tx * 8 + 4); }
    if (bias2) { c20 = *(const float4*)(bias2 + n0 + tx * 8);
                 c21 = *(const float4*)(bias2 + n0 + tx * 8 + 4); }
#pragma unroll
    for (int i = 0; i < 4; i++) {
        int mA = m0 + ty * 8 + 2 * i;
        float dA = 0.f, dB = 0.f;
        if (rp) {
            if (mA < Nn)     dA = (float)(rp[mA + 1] - rp[mA]);
            if (mA + 1 < Nn) dB = (float)(rp[mA + 2] - rp[mA + 1]);
        }
        float lo[8], hi[8];
#pragma unroll
        for (int j = 0; j < 8; j++) unpack2(acc[i][j], lo[j], hi[j]);
        float4 rA0 = make_float4(lo[0] + bb0.x + dA * c20.x, lo[1] + bb0.y + dA * c20.y,
                                 lo[2] + bb0.z + dA * c20.z, lo[3] + bb0.w + dA * c20.w);
        float4 rA1 = make_float4(lo[4] + bb1.x + dA * c21.x, lo[5] + bb1.y + dA * c21.y,
                                 lo[6] + bb1.z + dA * c21.z, lo[7] + bb1.w + dA * c21.w);
        float4 rB0 = make_float4(hi[0] + bb0.x + dB * c20.x, hi[1] + bb0.y + dB * c20.y,
                                 hi[2] + bb0.z + dB * c20.z, hi[3] + bb0.w + dB * c20.w);
        float4 rB1 = make_float4(hi[4] + bb1.x + dB * c21.x, hi[5] + bb1.y + dB * c21.y,
                                 hi[6] + bb1.z + dB * c21.z, hi[7] + bb1.w + dB * c21.w);
        *(float4*)(Cb + (size_t)mA * Nr + n0 + tx * 8)           = rA0;
        *(float4*)(Cb + (size_t)mA * Nr + n0 + tx * 8 + 4)       = rA1;
        *(float4*)(Cb + (size_t)(mA + 1) * Nr + n0 + tx * 8)     = rB0;
        *(float4*)(Cb + (size_t)(mA + 1) * Nr + n0 + tx * 8 + 4) = rB1;
    }
}

// ---------------- warp-per-node CSR edge kernel, tanh-silu ----------------
__global__ void __launch_bounds__(128)
edge_csr(const int* __restrict__ rp, const int* __restrict__ colp,
         const float* __restrict__ dvec, const float* __restrict__ y,
         const float2* __restrict__ tab, float* __restrict__ S) {
    int lane = threadIdx.x & 31;
    int n = blockIdx.x * 4 + (threadIdx.x >> 5);
    if (n >= Nn) return;
    int e0 = rp[n];
    int deg = rp[n + 1] - e0;
    const float* tf = (const float*)tab;
    float a0 = 0.f, a1 = 0.f, a2 = 0.f, a3 = 0.f;
    for (int base = 0; base < deg; base += 32) {
        int cnt = min(32, deg - base);
        float u_r = 0.f; int cc_r = 0;
        if (lane < cnt) {
            u_r = __ldg(dvec + e0 + base + lane) * SCALE;
            cc_r = __ldg(colp + e0 + base + lane);
        }
        for (int j = 0; j < cnt; j++) {
            float u = __shfl_sync(~0u, u_r, j);
            int cc = __shfl_sync(~0u, cc_r, j);
            int b = (int)u;
            float f = u - (float)b;
            const float4* trow = (const float4*)(tf + (b << 8)) + lane * 2;
            float4 t0 = __ldg(trow);
            float4 t1 = __ldg(trow + 1);
            float4 yv = __ldg((const float4*)(y + ((size_t)cc << 7)) + lane);
            float h0 = 0.5f * (yv.x + fmaf(f, t0.y, t0.x));
            float h1 = 0.5f * (yv.y + fmaf(f, t0.w, t0.z));
            float h2 = 0.5f * (yv.z + fmaf(f, t1.y, t1.x));
            float h3 = 0.5f * (yv.w + fmaf(f, t1.w, t1.z));
            a0 += fmaf(h0, tanhap(h0), h0);
            a1 += fmaf(h1, tanhap(h1), h1);
            a2 += fmaf(h2, tanhap(h2), h2);
            a3 += fmaf(h3, tanhap(h3), h3);
        }
    }
    *(float4*)(S + ((size_t)n << 7) + lane * 4) = make_float4(a0, a1, a2, a3);
}

// ---------------- fused GRU(l=3) + LayerNorm + pooling (+final via last block) ----------------
__global__ void __launch_bounds__(256)
ln_pool_all(const float* __restrict__ x, const float* __restrict__ gi,
            const float* __restrict__ bhh, const int* __restrict__ batch,
            const float* __restrict__ lg, const float* __restrict__ lb,
            float* __restrict__ out, float* __restrict__ sums,
            float* __restrict__ cnt, float* __restrict__ out2) {
    __shared__ int s_last;
    int warp = (blockIdx.x * blockDim.x + threadIdx.x) >> 5;
    int lane = threadIdx.x & 31;
    if (warp < Nn) {
        int ch = lane * 4;
        float4 v = __ldg((const float4*)(x + (size_t)warp * Hh + ch));
        const float* gm = gi + (size_t)warp * 384 + ch;
        float4 rv = __ldg((const float4*)(gm));
        float4 zv = __ldg((const float4*)(gm + 128));
        float4 nv = __ldg((const float4*)(gm + 256));
        float4 br = __ldg((const float4*)(bhh + ch));
        float4 bz = __ldg((const float4*)(bhh + 128 + ch));
        float4 bn = __ldg((const float4*)(bhh + 256 + ch));
        v.x = gru_upd(v.x, rv.x, zv.x, nv.x, br.x, bz.x, bn.x);
        v.y = gru_upd(v.y, rv.y, zv.y, nv.y, br.y, bz.y, bn.y);
        v.z = gru_upd(v.z, rv.z, zv.z, nv.z, br.z, bz.z, bn.z);
        v.w = gru_upd(v.w, rv.w, zv.w, nv.w, br.w, bz.w, bn.w);
        float s = v.x + v.y + v.z + v.w;
#pragma unroll
        for (int o = 16; o; o >>= 1) s += __shfl_xor_sync(~0u, s, o);
        float mu = s * (1.0f / 128.0f);
        float dx = v.x - mu, dy = v.y - mu, dz = v.z - mu, dw = v.w - mu;
        float vs = dx * dx + dy * dy + dz * dz + dw * dw;
#pragma unroll
        for (int o = 16; o; o >>= 1) vs += __shfl_xor_sync(~0u, vs, o);
        float inv = rsqrtf(vs * (1.0f / 128.0f) + 1e-5f);
        float o0 = dx * inv * lg[ch + 0] + lb[ch + 0];
        float o1 = dy * inv * lg[ch + 1] + lb[ch + 1];
        float o2 = dz * inv * lg[ch + 2] + lb[ch + 2];
        float o3 = dw * inv * lg[ch + 3] + lb[ch + 3];
        *(float4*)(out + (size_t)warp * Hh + ch) = make_float4(o0, o1, o2, o3);
        int bm = batch[warp];
        atomicAdd(&sums[bm * Hh + ch + 0], o0);
        atomicAdd(&sums[bm * Hh + ch + 1], o1);
        atomicAdd(&sums[bm * Hh + ch + 2], o2);
        atomicAdd(&sums[bm * Hh + ch + 3], o3);
        if (lane == 0) atomicAdd(&cnt[bm], 1.0f);
    }
    __syncthreads();
    if (threadIdx.x == 0) {
        __threadfence();
        int t = atomicAdd(&g_ctr, 1);
        s_last = (t == gridDim.x - 1) ? 1 : 0;
    }
    __syncthreads();
    if (s_last) {
        for (int i = threadIdx.x; i < Mm * Hh; i += blockDim.x) {
            float c = cnt[i >> 7];
            out2[i] = sums[i] / (c < 1.f ? 1.f : c);
        }
        if (threadIdx.x == 0) g_ctr = 0;
    }
}

// ---------------- host launcher ----------------
extern "C" void kernel_launch(void* const* d_in, const int* in_sizes, int n_in,
                              void* d_out, int out_size) {
    const int*   an    = (const int*)d_in[0];
    const float* pos   = (const float*)d_in[1];
    const int*   batch = (const int*)d_in[2];
    const int*   eidx  = (const int*)d_in[3];
    const float* emb   = (const float*)d_in[4];
    const float* W1    = (const float*)d_in[5];
    const float* b1    = (const float*)d_in[6];
    const float* W2    = (const float*)d_in[7];
    const float* b2    = (const float*)d_in[8];
    const float* W_ih  = (const float*)d_in[9];
    const float* b_ih  = (const float*)d_in[10];
    const float* b_hh  = (const float*)d_in[11];
    const float* ln_g  = (const float*)d_in[12];
    const float* ln_b  = (const float*)d_in[13];
    int E = in_sizes[3] / 2;
    if (E > EMAX) E = EMAX;
    const int* rowp = eidx;
    const int* colp = eidx + E;
    float* out = (float*)d_out;

    float *xp, *yp, *Sp, *gp, *dvp, *sp, *cp, *wcp, *bcp;
    float2* tp;
    int* rpp;
    cudaGetSymbolAddress((void**)&xp,  g_x);
    cudaGetSymbolAddress((void**)&yp,  g_y);
    cudaGetSymbolAddress((void**)&Sp,  g_S);
    cudaGetSymbolAddress((void**)&gp,  g_gi);
    cudaGetSymbolAddress((void**)&dvp, g_d);
    cudaGetSymbolAddress((void**)&rpp, g_rp);
    cudaGetSymbolAddress((void**)&sp,  g_sums);
    cudaGetSymbolAddress((void**)&cp,  g_cnt);
    cudaGetSymbolAddress((void**)&tp,  g_tab);
    cudaGetSymbolAddress((void**)&wcp, g_Wc);
    cudaGetSymbolAddress((void**)&bcp, g_bc2);

    // 1: init x/pads + zero sums/cnt + row_ptr
    int p0n = NP * Hh + Mm * Hh + Mm + E + 1;
    prep0<<<(p0n + 255) / 256, 256>>>(an, emb, rowp, E, xp, sp, cp, rpp);
    // 2: distances + float2 table (tiled) + bc2
    int ndb = (E + 127) / 128;
    prep1<<<ndb + (BINS / TBB) * Ll + 12, 128>>>(pos, rowp, colp, E, ndb,
                                                 W1, W_ih, b2, dvp, tp, bcp);
    const int Mt = NP / 128;
    for (int l = 0; l < Ll; l++) {
        const float* W1a = W1 + l * (Hh + Rr) * Hh;
        // y = x' @ W1a + b1   (x' = x + gru(gi_{l-1}) for l>0, stored back to x)
        gemm_f2b<<<dim3(1, Mt), 256>>>(xp, W1a, b1 + l * Hh, nullptr, nullptr,
                                       (l > 0) ? gp : nullptr,
                                       b_hh + (l - 1) * 3 * Hh, xp,
                                       yp, Hh, 0, 0, 0);
        // edge aggregation (warp-per-node CSR, tanh-silu)
        edge_csr<<<(Nn + 3) / 4, 128>>>(rpp, colp, dvp, yp, tp + l * BINS * Hh, Sp);
        if (l == 0) {
            // Wc[l] = W2[l] @ W_ih[l], batched over layers
            gemm_f2b<<<dim3(3, 1, Ll), 256>>>(W2, W_ih, nullptr, nullptr, nullptr,
                                              nullptr, nullptr, nullptr,
                                              wcp, 3 * Hh,
                                              Hh * Hh, Hh * 3 * Hh, Hh * 3 * Hh);
        }
        // gi = S @ Wc + b_ih + deg (x) bc2
        gemm_f2b<<<dim3(3, Mt), 256>>>(Sp, wcp + l * Hh * 3 * Hh, b_ih + l * 3 * Hh,
                                       rpp, bcp + l * 3 * Hh,
                                       nullptr, nullptr, nullptr,
                                       gp, 3 * Hh, 0, 0, 0);
    }

    float* out_x = out;
    float* out_rep = out + Nn * Hh;
    if (out_size == Mm * Hh) { out_x = yp; out_rep = out; }
    // fused GRU(l=3) + LayerNorm + pool + finalize
    ln_pool_all<<<(Nn + 7) / 8, 256>>>(xp, gp, b_hh + 3 * 3 * Hh, batch,
                                       ln_g, ln_b, out_x, sp, cp, out_rep);
}

// round 9
// speedup vs baseline: 4.4301x; 1.0078x over previous
#include <cuda_runtime.h>
#include <cuda_bf16.h>
#include <math.h>

#define Hh 128
#define Rr 50
#define Ll 4
#define Nn 10000
#define Mm 64
#define NP 10112           // 79 * 128
#define EMAX 2000000
#define BINS 2048
#define SCALE ((float)BINS / 5.0f)
#define STEP (5.0f / (float)BINS)
#define TBB 64             // bins per table-build block

typedef unsigned long long u64;

__device__ __forceinline__ void fma2(u64 &d, u64 a, u64 b) {
    asm("fma.rn.f32x2 %0, %1, %2, %0;" : "+l"(d) : "l"(a), "l"(b));
}
__device__ __forceinline__ u64 pack2(float lo, float hi) {
    u64 r; asm("mov.b64 %0, {%1, %2};" : "=l"(r) : "f"(lo), "f"(hi)); return r;
}
__device__ __forceinline__ void unpack2(u64 v, float &lo, float &hi) {
    asm("mov.b64 {%0, %1}, %2;" : "=f"(lo), "=f"(hi) : "l"(v));
}
__device__ __forceinline__ float tanhap(float x) {
    float r; asm("tanh.approx.f32 %0, %1;" : "=f"(r) : "f"(x)); return r;
}

__device__ __forceinline__ float gru_upd(float xo, float rv, float zv, float nv,
                                         float bhr, float bhz, float bhn) {
    float r = __fdividef(1.f, 1.f + __expf(-(rv + bhr)));
    float z = __fdividef(1.f, 1.f + __expf(-(zv + bhz)));
    float t = nv + r * bhn;
    float e = __expf(2.f * t);
    float th = 1.f - __fdividef(2.f, e + 1.f);
    return xo + (1.f - z) * th;
}

// ---------------- scratch ----------------
__device__ float  g_x[NP * Hh];
__device__ float  g_y[NP * Hh];
__device__ float  g_S[NP * Hh];
__device__ float  g_gi[NP * 3 * Hh];
__device__ float  g_d[EMAX];
__device__ int    g_rp[Nn + 1];
__device__ float  g_sums[Mm * Hh];
__device__ float  g_cnt[Mm];
__device__ float2 g_tab[Ll * BINS * Hh];
__device__ float  g_Wc[Ll * Hh * 3 * Hh];
__device__ float  g_bc2[Ll * 3 * Hh];
__device__ int    g_ctr;

// ---------------- prep0: init x (+pads), zero sums/cnt, build row_ptr ----------------
__global__ void prep0(const int* __restrict__ an, const float* __restrict__ emb,
                      const int* __restrict__ rowp, int E,
                      float* __restrict__ x, float* __restrict__ sums,
                      float* __restrict__ cnt, int* __restrict__ rp) {
    int i = blockIdx.x * blockDim.x + threadIdx.x;
    if (i < NP * Hh) {
        int n = i >> 7, ch = i & 127;
        if (n < Nn) {
            int a = an[n];
            a = a < 0 ? 0 : (a > 99 ? 99 : a);
            x[i] = emb[a * Hh + ch];
        } else {
            x[i] = 0.f;
        }
        return;
    }
    int i2 = i - NP * Hh;
    if (i2 < Mm * Hh) { sums[i2] = 0.f; return; }
    i2 -= Mm * Hh;
    if (i2 < Mm) { cnt[i2] = 0.f; return; }
    int e = i2 - Mm;
    if (e > E) return;
    if (e == 0) {
        int b = rowp[0];
        for (int r = 0; r <= b; r++) rp[r] = 0;
    } else if (e == E) {
        int a = rowp[E - 1];
        for (int r = a + 1; r <= Nn; r++) rp[r] = E;
    } else {
        int a = rowp[e - 1], b = rowp[e];
        for (int r = a + 1; r <= b; r++) rp[r] = e;
    }
}

// ---------------- prep1: distances + float2 rbf table (tiled) + bc2 ----------------
__global__ void prep1(const float* __restrict__ pos, const int* __restrict__ rowp,
                      const int* __restrict__ colp, int E, int ndb,
                      const float* __restrict__ W1, const float* __restrict__ W_ih,
                      const float* __restrict__ b2,
                      float* __restrict__ dv, float2* __restrict__ tab,
                      float* __restrict__ bc2) {
    __shared__ float basis[(TBB + 1) * Rr];
    int tid = threadIdx.x;
    int blk = blockIdx.x;
    if (blk < ndb) {
        int e = blk * 128 + tid;
        if (e < E) {
            int r = rowp[e], c = colp[e];
            float dx = pos[r * 3 + 0] - pos[c * 3 + 0];
            float dy = pos[r * 3 + 1] - pos[c * 3 + 1];
            float dz = pos[r * 3 + 2] - pos[c * 3 + 2];
            dv[e] = sqrtf(dx * dx + dy * dy + dz * dz);
        }
        return;
    }
    int t = blk - ndb;
    const int TBLKS = BINS / TBB;                 // 32 per layer
    if (t < TBLKS * Ll) {
        int l = t / TBLKS, bt = t - l * TBLKS;
        int bin0 = bt * TBB;
        for (int i = tid; i < (TBB + 1) * Rr; i += 128) {
            int g = i / Rr, k = i - g * Rr;
            float c = (float)k * (5.0f / 49.0f);
            float d0 = (float)(bin0 + g) * STEP - c;
            basis[i] = expf(-50.0f * d0 * d0);
        }
        __syncthreads();
        const float* W1b = W1 + l * (Hh + Rr) * Hh + Hh * Hh;
        float w[Rr];
#pragma unroll
        for (int k = 0; k < Rr; k++) w[k] = W1b[k * Hh + tid];
        float vprev = 0.f;
#pragma unroll
        for (int k = 0; k < Rr; k++) vprev += basis[k] * w[k];
        for (int g = 1; g <= TBB; g++) {
            float v = 0.f;
            const float* bs = &basis[g * Rr];
#pragma unroll
            for (int k = 0; k < Rr; k++) v += bs[k] * w[k];
            tab[((l * BINS + bin0 + g - 1) << 7) + tid] = make_float2(vprev, v - vprev);
            vprev = v;
        }
        return;
    }
    int t2 = t - TBLKS * Ll;           // [0, 12): bc2 = b2 @ W_ih
    int l = t2 / 3, chunk = t2 - l * 3;
    int n = chunk * 128 + tid;
    const float* W = W_ih + l * Hh * 3 * Hh;
    const float* b = b2 + l * Hh;
    float s = 0.f;
#pragma unroll 8
    for (int k = 0; k < Hh; k++) s += b[k] * W[k * 3 * Hh + n];
    bc2[l * 3 * Hh + n] = s;
}

// ---------------- f32x2 GEMM, tile 128x128, optional fused GRU prologue ----------------
__global__ void __launch_bounds__(256, 2)
gemm_f2b(const float* __restrict__ A, const float* __restrict__ B,
         const float* __restrict__ bias, const int* __restrict__ rp,
         const float* __restrict__ bias2,
         const float* __restrict__ gi, const float* __restrict__ bhh,
         float* __restrict__ xout,
         float* __restrict__ C, int Nr,
         int aSz, int bSz, int cSz) {
    __shared__ float As[16][132];
    __shared__ float Bs[16][128];
    int tid = threadIdx.x;
    int tx = tid & 15, ty = tid >> 4;
    int m0 = blockIdx.y * 128, n0 = blockIdx.x * 128;
    const float* Ab = A + (size_t)blockIdx.z * aSz;
    const float* Bb = B + (size_t)blockIdx.z * bSz;
    float* Cb = C + (size_t)blockIdx.z * cSz;
    u64 acc[4][8] = {};
    for (int kk = 0; kk < 128; kk += 16) {
#pragma unroll
        for (int it = 0; it < 2; it++) {
            int r = (tid >> 2) + it * 64;
            int c4 = (tid & 3) << 2;
            int m = m0 + r;
            float4 v = *(const float4*)(Ab + (size_t)m * 128 + kk + c4);
            if (gi) {
                const float* gm = gi + (size_t)m * 384 + kk + c4;
                float4 rv = __ldg((const float4*)(gm));
                float4 zv = __ldg((const float4*)(gm + 128));
                float4 nv = __ldg((const float4*)(gm + 256));
                float4 br = __ldg((const float4*)(bhh + kk + c4));
                float4 bz = __ldg((const float4*)(bhh + 128 + kk + c4));
                float4 bn = __ldg((const float4*)(bhh + 256 + kk + c4));
                v.x = gru_upd(v.x, rv.x, zv.x, nv.x, br.x, bz.x, bn.x);
                v.y = gru_upd(v.y, rv.y, zv.y, nv.y, br.y, bz.y, bn.y);
                v.z = gru_upd(v.z, rv.z, zv.z, nv.z, br.z, bz.z, bn.z);
                v.w = gru_upd(v.w, rv.w, zv.w, nv.w, br.w, bz.w, bn.w);
                *(float4*)(xout + (size_t)m * 128 + kk + c4) = v;
            }
            As[c4 + 0][r] = v.x; As[c4 + 1][r] = v.y;
            As[c4 + 2][r] = v.z; As[c4 + 3][r] = v.w;
        }
        {
            int r = tid >> 4, c8 = (tid & 15) << 3;
            *(float4*)&Bs[r][c8]     = *(const float4*)(Bb + (size_t)(kk + r) * Nr + n0 + c8);
            *(float4*)&Bs[r][c8 + 4] = *(const float4*)(Bb + (size_t)(kk + r) * Nr + n0 + c8 + 4);
        }
        __syncthreads();
#pragma unroll
        for (int k = 0; k < 16; k++) {
            longlong2 la = *(const longlong2*)&As[k][ty * 8];
            longlong2 lb = *(const longlong2*)&As[k][ty * 8 + 4];
            float4 b0 = *(const float4*)&Bs[k][tx * 8];
            float4 b1 = *(const float4*)&Bs[k][tx * 8 + 4];
            u64 ap[4] = { (u64)la.x, (u64)la.y, (u64)lb.x, (u64)lb.y };
            u64 bp[8] = { pack2(b0.x, b0.x), pack2(b0.y, b0.y),
                          pack2(b0.z, b0.z), pack2(b0.w, b0.w),
                          pack2(b1.x, b1.x), pack2(b1.y, b1.y),
                          pack2(b1.z, b1.z), pack2(b1.w, b1.w) };
#pragma unroll
            for (int i = 0; i < 4; i++)
#pragma unroll
                for (int j = 0; j < 8; j++) fma2(acc[i][j], ap[i], bp[j]);
        }
        __syncthreads();
    }
    float4 bb0 = make_float4(0.f, 0.f, 0.f, 0.f), bb1 = bb0;
    float4 c20 = bb0, c21 = bb0;
    if (bias)  { bb0 = *(const float4*)(bias + n0 + tx * 8);
                 bb1 = *(const float4*)(bias + n0 + tx * 8 + 4); }
    if (bias2) { c20 = *(const float4*)(bias2 + n0 + tx * 8);
                 c21 = *(const float4*)(bias2 + n0 + tx * 8 + 4); }
#pragma unroll
    for (int i = 0; i < 4; i++) {
        int mA = m0 + ty * 8 + 2 * i;
        float dA = 0.f, dB = 0.f;
        if (rp) {
            if (mA < Nn)     dA = (float)(rp[mA + 1] - rp[mA]);
            if (mA + 1 < Nn) dB = (float)(rp[mA + 2] - rp[mA + 1]);
        }
        float lo[8], hi[8];
#pragma unroll
        for (int j = 0; j < 8; j++) unpack2(acc[i][j], lo[j], hi[j]);
        float4 rA0 = make_float4(lo[0] + bb0.x + dA * c20.x, lo[1] + bb0.y + dA * c20.y,
                                 lo[2] + bb0.z + dA * c20.z, lo[3] + bb0.w + dA * c20.w);
        float4 rA1 = make_float4(lo[4] + bb1.x + dA * c21.x, lo[5] + bb1.y + dA * c21.y,
                                 lo[6] + bb1.z + dA * c21.z, lo[7] + bb1.w + dA * c21.w);
        float4 rB0 = make_float4(hi[0] + bb0.x + dB * c20.x, hi[1] + bb0.y + dB * c20.y,
                                 hi[2] + bb0.z + dB * c20.z, hi[3] + bb0.w + dB * c20.w);
        float4 rB1 = make_float4(hi[4] + bb1.x + dB * c21.x, hi[5] + bb1.y + dB * c21.y,
                                 hi[6] + bb1.z + dB * c21.z, hi[7] + bb1.w + dB * c21.w);
        *(float4*)(Cb + (size_t)mA * Nr + n0 + tx * 8)           = rA0;
        *(float4*)(Cb + (size_t)mA * Nr + n0 + tx * 8 + 4)       = rA1;
        *(float4*)(Cb + (size_t)(mA + 1) * Nr + n0 + tx * 8)     = rB0;
        *(float4*)(Cb + (size_t)(mA + 1) * Nr + n0 + tx * 8 + 4) = rB1;
    }
}

// ---------------- warp-per-node CSR edge kernel, 4-edge software pipeline ----------------
__global__ void __launch_bounds__(128)
edge_csr(const int* __restrict__ rp, const int* __restrict__ colp,
         const float* __restrict__ dvec, const float* __restrict__ y,
         const float2* __restrict__ tab, float* __restrict__ S) {
    int lane = threadIdx.x & 31;
    int n = blockIdx.x * 4 + (threadIdx.x >> 5);
    if (n >= Nn) return;
    int e0 = rp[n];
    int deg = rp[n + 1] - e0;
    const float* tf = (const float*)tab;
    float a0 = 0.f, a1 = 0.f, a2 = 0.f, a3 = 0.f;
    for (int base = 0; base < deg; base += 32) {
        int cnt = min(32, deg - base);
        float u_r = 0.f; int cc_r = 0;
        if (lane < cnt) {
            u_r = __ldg(dvec + e0 + base + lane) * SCALE;
            cc_r = __ldg(colp + e0 + base + lane);
        }
        int j = 0;
        for (; j + 4 <= cnt; j += 4) {
            float u0 = __shfl_sync(~0u, u_r, j);
            float u1 = __shfl_sync(~0u, u_r, j + 1);
            float u2 = __shfl_sync(~0u, u_r, j + 2);
            float u3 = __shfl_sync(~0u, u_r, j + 3);
            int c0 = __shfl_sync(~0u, cc_r, j);
            int c1 = __shfl_sync(~0u, cc_r, j + 1);
            int c2 = __shfl_sync(~0u, cc_r, j + 2);
            int c3 = __shfl_sync(~0u, cc_r, j + 3);
            int b0i = (int)u0, b1i = (int)u1, b2i = (int)u2, b3i = (int)u3;
            float f0 = u0 - (float)b0i, f1 = u1 - (float)b1i;
            float f2 = u2 - (float)b2i, f3 = u3 - (float)b3i;
            const float4* tr0 = (const float4*)(tf + (b0i << 8)) + lane * 2;
            const float4* tr1 = (const float4*)(tf + (b1i << 8)) + lane * 2;
            const float4* tr2 = (const float4*)(tf + (b2i << 8)) + lane * 2;
            const float4* tr3 = (const float4*)(tf + (b3i << 8)) + lane * 2;
            // issue all 12 loads before any compute (MLP = 12)
            float4 tA0 = __ldg(tr0), tA1 = __ldg(tr0 + 1);
            float4 tB0 = __ldg(tr1), tB1 = __ldg(tr1 + 1);
            float4 tC0 = __ldg(tr2), tC1 = __ldg(tr2 + 1);
            float4 tD0 = __ldg(tr3), tD1 = __ldg(tr3 + 1);
            float4 yA = __ldg((const float4*)(y + ((size_t)c0 << 7)) + lane);
            float4 yB = __ldg((const float4*)(y + ((size_t)c1 << 7)) + lane);
            float4 yC = __ldg((const float4*)(y + ((size_t)c2 << 7)) + lane);
            float4 yD = __ldg((const float4*)(y + ((size_t)c3 << 7)) + lane);
            float h;
            h = 0.5f * (yA.x + fmaf(f0, tA0.y, tA0.x)); a0 += fmaf(h, tanhap(h), h);
            h = 0.5f * (yA.y + fmaf(f0, tA0.w, tA0.z)); a1 += fmaf(h, tanhap(h), h);
            h = 0.5f * (yA.z + fmaf(f0, tA1.y, tA1.x)); a2 += fmaf(h, tanhap(h), h);
            h = 0.5f * (yA.w + fmaf(f0, tA1.w, tA1.z)); a3 += fmaf(h, tanhap(h), h);
            h = 0.5f * (yB.x + fmaf(f1, tB0.y, tB0.x)); a0 += fmaf(h, tanhap(h), h);
            h = 0.5f * (yB.y + fmaf(f1, tB0.w, tB0.z)); a1 += fmaf(h, tanhap(h), h);
            h = 0.5f * (yB.z + fmaf(f1, tB1.y, tB1.x)); a2 += fmaf(h, tanhap(h), h);
            h = 0.5f * (yB.w + fmaf(f1, tB1.w, tB1.z)); a3 += fmaf(h, tanhap(h), h);
            h = 0.5f * (yC.x + fmaf(f2, tC0.y, tC0.x)); a0 += fmaf(h, tanhap(h), h);
            h = 0.5f * (yC.y + fmaf(f2, tC0.w, tC0.z)); a1 += fmaf(h, tanhap(h), h);
            h = 0.5f * (yC.z + fmaf(f2, tC1.y, tC1.x)); a2 += fmaf(h, tanhap(h), h);
            h = 0.5f * (yC.w + fmaf(f2, tC1.w, tC1.z)); a3 += fmaf(h, tanhap(h), h);
            h = 0.5f * (yD.x + fmaf(f3, tD0.y, tD0.x)); a0 += fmaf(h, tanhap(h), h);
            h = 0.5f * (yD.y + fmaf(f3, tD0.w, tD0.z)); a1 += fmaf(h, tanhap(h), h);
            h = 0.5f * (yD.z + fmaf(f3, tD1.y, tD1.x)); a2 += fmaf(h, tanhap(h), h);
            h = 0.5f * (yD.w + fmaf(f3, tD1.w, tD1.z)); a3 += fmaf(h, tanhap(h), h);
        }
        for (; j < cnt; j++) {
            float u = __shfl_sync(~0u, u_r, j);
            int cc = __shfl_sync(~0u, cc_r, j);
            int b = (int)u;
            float f = u - (float)b;
            const float4* trow = (const float4*)(tf + (b << 8)) + lane * 2;
            float4 t0 = __ldg(trow);
            float4 t1 = __ldg(trow + 1);
            float4 yv = __ldg((const float4*)(y + ((size_t)cc << 7)) + lane);
            float h0 = 0.5f * (yv.x + fmaf(f, t0.y, t0.x));
            float h1 = 0.5f * (yv.y + fmaf(f, t0.w, t0.z));
            float h2 = 0.5f * (yv.z + fmaf(f, t1.y, t1.x));
            float h3 = 0.5f * (yv.w + fmaf(f, t1.w, t1.z));
            a0 += fmaf(h0, tanhap(h0), h0);
            a1 += fmaf(h1, tanhap(h1), h1);
            a2 += fmaf(h2, tanhap(h2), h2);
            a3 += fmaf(h3, tanhap(h3), h3);
        }
    }
    *(float4*)(S + ((size_t)n << 7) + lane * 4) = make_float4(a0, a1, a2, a3);
}

// ---------------- fused GRU(l=3) + LayerNorm + pooling (+final via last block) ----------------
__global__ void __launch_bounds__(256)
ln_pool_all(const float* __restrict__ x, const float* __restrict__ gi,
            const float* __restrict__ bhh, const int* __restrict__ batch,
            const float* __restrict__ lg, const float* __restrict__ lb,
            float* __restrict__ out, float* __restrict__ sums,
            float* __restrict__ cnt, float* __restrict__ out2) {
    __shared__ int s_last;
    int warp = (blockIdx.x * blockDim.x + threadIdx.x) >> 5;
    int lane = threadIdx.x & 31;
    if (warp < Nn) {
        int ch = lane * 4;
        float4 v = __ldg((const float4*)(x + (size_t)warp * Hh + ch));
        const float* gm = gi + (size_t)warp * 384 + ch;
        float4 rv = __ldg((const float4*)(gm));
        float4 zv = __ldg((const float4*)(gm + 128));
        float4 nv = __ldg((const float4*)(gm + 256));
        float4 br = __ldg((const float4*)(bhh + ch));
        float4 bz = __ldg((const float4*)(bhh + 128 + ch));
        float4 bn = __ldg((const float4*)(bhh + 256 + ch));
        v.x = gru_upd(v.x, rv.x, zv.x, nv.x, br.x, bz.x, bn.x);
        v.y = gru_upd(v.y, rv.y, zv.y, nv.y, br.y, bz.y, bn.y);
        v.z = gru_upd(v.z, rv.z, zv.z, nv.z, br.z, bz.z, bn.z);
        v.w = gru_upd(v.w, rv.w, zv.w, nv.w, br.w, bz.w, bn.w);
        float s = v.x + v.y + v.z + v.w;
#pragma unroll
        for (int o = 16; o; o >>= 1) s += __shfl_xor_sync(~0u, s, o);
        float mu = s * (1.0f / 128.0f);
        float dx = v.x - mu, dy = v.y - mu, dz = v.z - mu, dw = v.w - mu;
        float vs = dx * dx + dy * dy + dz * dz + dw * dw;
#pragma unroll
        for (int o = 16; o; o >>= 1) vs += __shfl_xor_sync(~0u, vs, o);
        float inv = rsqrtf(vs * (1.0f / 128.0f) + 1e-5f);
        float o0 = dx * inv * lg[ch + 0] + lb[ch + 0];
        float o1 = dy * inv * lg[ch + 1] + lb[ch + 1];
        float o2 = dz * inv * lg[ch + 2] + lb[ch + 2];
        float o3 = dw * inv * lg[ch + 3] + lb[ch + 3];
        *(float4*)(out + (size_t)warp * Hh + ch) = make_float4(o0, o1, o2, o3);
        int bm = batch[warp];
        atomicAdd(&sums[bm * Hh + ch + 0], o0);
        atomicAdd(&sums[bm * Hh + ch + 1], o1);
        atomicAdd(&sums[bm * Hh + ch + 2], o2);
        atomicAdd(&sums[bm * Hh + ch + 3], o3);
        if (lane == 0) atomicAdd(&cnt[bm], 1.0f);
    }
    __syncthreads();
    if (threadIdx.x == 0) {
        __threadfence();
        int t = atomicAdd(&g_ctr, 1);
        s_last = (t == gridDim.x - 1) ? 1 : 0;
    }
    __syncthreads();
    if (s_last) {
        for (int i = threadIdx.x; i < Mm * Hh; i += blockDim.x) {
            float c = cnt[i >> 7];
            out2[i] = sums[i] / (c < 1.f ? 1.f : c);
        }
        if (threadIdx.x == 0) g_ctr = 0;
    }
}

// ---------------- host launcher ----------------
extern "C" void kernel_launch(void* const* d_in, const int* in_sizes, int n_in,
                              void* d_out, int out_size) {
    const int*   an    = (const int*)d_in[0];
    const float* pos   = (const float*)d_in[1];
    const int*   batch = (const int*)d_in[2];
    const int*   eidx  = (const int*)d_in[3];
    const float* emb   = (const float*)d_in[4];
    const float* W1    = (const float*)d_in[5];
    const float* b1    = (const float*)d_in[6];
    const float* W2    = (const float*)d_in[7];
    const float* b2    = (const float*)d_in[8];
    const float* W_ih  = (const float*)d_in[9];
    const float* b_ih  = (const float*)d_in[10];
    const float* b_hh  = (const float*)d_in[11];
    const float* ln_g  = (const float*)d_in[12];
    const float* ln_b  = (const float*)d_in[13];
    int E = in_sizes[3] / 2;
    if (E > EMAX) E = EMAX;
    const int* rowp = eidx;
    const int* colp = eidx + E;
    float* out = (float*)d_out;

    float *xp, *yp, *Sp, *gp, *dvp, *sp, *cp, *wcp, *bcp;
    float2* tp;
    int* rpp;
    cudaGetSymbolAddress((void**)&xp,  g_x);
    cudaGetSymbolAddress((void**)&yp,  g_y);
    cudaGetSymbolAddress((void**)&Sp,  g_S);
    cudaGetSymbolAddress((void**)&gp,  g_gi);
    cudaGetSymbolAddress((void**)&dvp, g_d);
    cudaGetSymbolAddress((void**)&rpp, g_rp);
    cudaGetSymbolAddress((void**)&sp,  g_sums);
    cudaGetSymbolAddress((void**)&cp,  g_cnt);
    cudaGetSymbolAddress((void**)&tp,  g_tab);
    cudaGetSymbolAddress((void**)&wcp, g_Wc);
    cudaGetSymbolAddress((void**)&bcp, g_bc2);

    // 1: init x/pads + zero sums/cnt + row_ptr
    int p0n = NP * Hh + Mm * Hh + Mm + E + 1;
    prep0<<<(p0n + 255) / 256, 256>>>(an, emb, rowp, E, xp, sp, cp, rpp);
    // 2: distances + float2 table (tiled) + bc2
    int ndb = (E + 127) / 128;
    prep1<<<ndb + (BINS / TBB) * Ll + 12, 128>>>(pos, rowp, colp, E, ndb,
                                                 W1, W_ih, b2, dvp, tp, bcp);
    const int Mt = NP / 128;
    for (int l = 0; l < Ll; l++) {
        const float* W1a = W1 + l * (Hh + Rr) * Hh;
        // y = x' @ W1a + b1   (x' = x + gru(gi_{l-1}) for l>0, stored back to x)
        gemm_f2b<<<dim3(1, Mt), 256>>>(xp, W1a, b1 + l * Hh, nullptr, nullptr,
                                       (l > 0) ? gp : nullptr,
                                       b_hh + (l - 1) * 3 * Hh, xp,
                                       yp, Hh, 0, 0, 0);
        // edge aggregation (warp-per-node CSR, 4-edge pipeline)
        edge_csr<<<(Nn + 3) / 4, 128>>>(rpp, colp, dvp, yp, tp + l * BINS * Hh, Sp);
        if (l == 0) {
            // Wc[l] = W2[l] @ W_ih[l], batched over layers
            gemm_f2b<<<dim3(3, 1, Ll), 256>>>(W2, W_ih, nullptr, nullptr, nullptr,
                                              nullptr, nullptr, nullptr,
                                              wcp, 3 * Hh,
                                              Hh * Hh, Hh * 3 * Hh, Hh * 3 * Hh);
        }
        // gi = S @ Wc + b_ih + deg (x) bc2
        gemm_f2b<<<dim3(3, Mt), 256>>>(Sp, wcp + l * Hh * 3 * Hh, b_ih + l * 3 * Hh,
                                       rpp, bcp + l * 3 * Hh,
                                       nullptr, nullptr, nullptr,
                                       gp, 3 * Hh, 0, 0, 0);
    }

    float* out_x = out;
    float* out_rep = out + Nn * Hh;
    if (out_size == Mm * Hh) { out_x = yp; out_rep = out; }
    // fused GRU(l=3) + LayerNorm + pool + finalize
    ln_pool_all<<<(Nn + 7) / 8, 256>>>(xp, gp, b_hh + 3 * 3 * Hh, batch,
                                       ln_g, ln_b, out_x, sp, cp, out_rep);
}